// round 13
// baseline (speedup 1.0000x reference)
#include <cuda_runtime.h>
#include <cuda_fp16.h>
#include <cstdint>

// Problem constants
#define B_    8
#define CIN   64
#define COUT  64
#define L_    16384
#define KK    5
#define PAD_  2
#define LP    (L_ + 2*PAD_)
#define TP    256
#define NTHR  512

// x slice in smem (fp16, 128B rows, XOR-swizzled 16B units)
#define SPAN  272
#define MARG  6          // base = lo0 - MARG

// smem byte offsets
#define SM_XS    0                 // 272*128 = 34816
#define SM_A     34816             // 2 bufs * 256 rows * 128B = 65536
#define SM_PAR   100352            // 5*256*8 = 10240
#define SM_TOTAL 110592
#define A_STR    32768

// swizzle of 16B units within a 128B row
#define SWZ16(col, row) ((col) ^ (((row) & 7) * 16))

// W in mma-B fragment order: [tap][ngrp][ks][h][lane] -> uint4
__device__ uint4 g_wf[KK * 2 * 4 * 2 * 32];

// ---------------------------------------------------------------------------
// weight (o,c,k) -> fragment-ordered fp16
// ---------------------------------------------------------------------------
__global__ void wfrag_kernel(const float* __restrict__ w) {
    int idx = blockIdx.x * 256 + threadIdx.x;    // 2560 entries
    if (idx >= 2560) return;
    int lane = idx & 31;
    int h    = (idx >> 5) & 1;
    int ks   = (idx >> 6) & 3;
    int ngrp = (idx >> 8) & 1;
    int tap  = idx >> 9;
    int bn = lane >> 2;
    int q2 = (lane & 3) * 2;
    uint32_t r[4];
    #pragma unroll
    for (int j = 0; j < 2; j++) {
        int n = ngrp * 32 + (h * 2 + j) * 8 + bn;
        #pragma unroll
        for (int hf = 0; hf < 2; hf++) {
            int c0 = ks * 16 + hf * 8 + q2;
            __half2 p;
            p.x = __float2half_rn(w[n * (CIN * KK) + c0 * KK + tap]);
            p.y = __float2half_rn(w[n * (CIN * KK) + (c0 + 1) * KK + tap]);
            r[j * 2 + hf] = *(uint32_t*)&p;
        }
    }
    g_wf[idx] = make_uint4(r[0], r[1], r[2], r[3]);
}

// ---------------------------------------------------------------------------
__device__ __forceinline__ void ldm_x4(uint32_t& r0, uint32_t& r1, uint32_t& r2, uint32_t& r3,
                                       const void* p) {
    uint32_t a = (uint32_t)__cvta_generic_to_shared(p);
    asm volatile("ldmatrix.sync.aligned.m8n8.x4.shared.b16 {%0,%1,%2,%3}, [%4];"
                 : "=r"(r0), "=r"(r1), "=r"(r2), "=r"(r3) : "r"(a));
}

__device__ __forceinline__ void mma_fp16(float* c, const uint32_t* a,
                                         uint32_t b0, uint32_t b1) {
    asm volatile(
        "mma.sync.aligned.m16n8k16.row.col.f32.f16.f16.f32 "
        "{%0,%1,%2,%3}, {%4,%5,%6,%7}, {%8,%9}, {%0,%1,%2,%3};"
        : "+f"(c[0]), "+f"(c[1]), "+f"(c[2]), "+f"(c[3])
        : "r"(a[0]), "r"(a[1]), "r"(a[2]), "r"(a[3]), "r"(b0), "r"(b1));
}

// ---------------------------------------------------------------------------
// build full-tap A tile (256 pos x 64 ch). 8 channels/thread, LDS.128 gathers.
// ---------------------------------------------------------------------------
__device__ __forceinline__ void build_tap(char* sm, const float* __restrict__ xb,
                                          int base, int tap, int buf, int t) {
    const int cq = t & 7;           // 8 channels: 8*cq .. 8*cq+7
    const int pb = t >> 3;          // 64 position groups
    const uint2* par = (const uint2*)(sm + SM_PAR) + tap * TP;
    char* A = sm + SM_A + buf * A_STR;
    const int cabs = cq * 8;
    const int swc  = SWZ16(cq * 16, pb);   // p&7 == pb&7 (pi stride 64)

    #pragma unroll
    for (int pi = 0; pi < 4; pi++) {
        int p = pb + pi * 64;
        uint2 pr = par[p];
        int j0 = (int)(short)(pr.x & 0xFFFF);
        int j1 = (int)(short)(pr.x >> 16);
        __half2 f2 = __half2half2(__ushort_as_half((unsigned short)pr.y));
        uint4 u0, u1;
        if (__builtin_expect((unsigned)j0 < SPAN, 1)) {
            u0 = *(const uint4*)(sm + SM_XS + j0 * 128 + SWZ16(cq * 16, j0));
        } else {
            int ja = min(max(j0 + base, 0), L_ - 1);
            __half2 h01 = __floats2half2_rn(xb[(size_t)cabs * L_ + ja],
                                            xb[(size_t)(cabs + 1) * L_ + ja]);
            __half2 h23 = __floats2half2_rn(xb[(size_t)(cabs + 2) * L_ + ja],
                                            xb[(size_t)(cabs + 3) * L_ + ja]);
            __half2 h45 = __floats2half2_rn(xb[(size_t)(cabs + 4) * L_ + ja],
                                            xb[(size_t)(cabs + 5) * L_ + ja]);
            __half2 h67 = __floats2half2_rn(xb[(size_t)(cabs + 6) * L_ + ja],
                                            xb[(size_t)(cabs + 7) * L_ + ja]);
            u0.x = *(uint32_t*)&h01; u0.y = *(uint32_t*)&h23;
            u0.z = *(uint32_t*)&h45; u0.w = *(uint32_t*)&h67;
        }
        if (__builtin_expect((unsigned)j1 < SPAN, 1)) {
            u1 = *(const uint4*)(sm + SM_XS + j1 * 128 + SWZ16(cq * 16, j1));
        } else {
            int ja = min(max(j1 + base, 0), L_ - 1);
            __half2 h01 = __floats2half2_rn(xb[(size_t)cabs * L_ + ja],
                                            xb[(size_t)(cabs + 1) * L_ + ja]);
            __half2 h23 = __floats2half2_rn(xb[(size_t)(cabs + 2) * L_ + ja],
                                            xb[(size_t)(cabs + 3) * L_ + ja]);
            __half2 h45 = __floats2half2_rn(xb[(size_t)(cabs + 4) * L_ + ja],
                                            xb[(size_t)(cabs + 5) * L_ + ja]);
            __half2 h67 = __floats2half2_rn(xb[(size_t)(cabs + 6) * L_ + ja],
                                            xb[(size_t)(cabs + 7) * L_ + ja]);
            u1.x = *(uint32_t*)&h01; u1.y = *(uint32_t*)&h23;
            u1.z = *(uint32_t*)&h45; u1.w = *(uint32_t*)&h67;
        }
        __half2 g0, g1;
        uint4 st;
        g0 = *(__half2*)&u0.x; g1 = *(__half2*)&u1.x;
        { __half2 v = __hfma2(f2, __hsub2(g1, g0), g0); st.x = *(uint32_t*)&v; }
        g0 = *(__half2*)&u0.y; g1 = *(__half2*)&u1.y;
        { __half2 v = __hfma2(f2, __hsub2(g1, g0), g0); st.y = *(uint32_t*)&v; }
        g0 = *(__half2*)&u0.z; g1 = *(__half2*)&u1.z;
        { __half2 v = __hfma2(f2, __hsub2(g1, g0), g0); st.z = *(uint32_t*)&v; }
        g0 = *(__half2*)&u0.w; g1 = *(__half2*)&u1.w;
        { __half2 v = __hfma2(f2, __hsub2(g1, g0), g0); st.w = *(uint32_t*)&v; }
        *(uint4*)(A + p * 128 + swc) = st;
    }
}

// ---------------------------------------------------------------------------
__global__ __launch_bounds__(NTHR, 2) void deform_main_kernel(
    const float* __restrict__ x,
    const float* __restrict__ off,
    const float* __restrict__ bias,
    float* __restrict__ out)
{
    extern __shared__ char sm[];

    const int b    = blockIdx.y;
    const int lo0  = blockIdx.x * TP;
    const int t    = threadIdx.x;
    const int lane = t & 31;
    const int wid  = t >> 5;
    const int base = lo0 - MARG;

    const float* xb = x + (size_t)b * CIN * L_;
    uint2* par = (uint2*)(sm + SM_PAR);

    // ---- x slice -> fp16 swizzled smem ----
    // per warp one channel-pair row; lanes sweep q (coalesced LDG, 4-way-max STS)
    {
        bool interior = (base >= 0) && (base + SPAN <= L_);
        for (int i = wid; i < 32; i += 16) {          // channel pair i: ch 2i, 2i+1
            const float* r0 = xb + (size_t)(2 * i) * L_;
            const float* r1 = r0 + L_;
            for (int q = lane; q < SPAN; q += 32) {
                float v0, v1;
                if (interior) {
                    v0 = r0[base + q];
                    v1 = r1[base + q];
                } else {
                    int ja = min(max(base + q, 0), L_ - 1);
                    v0 = r0[ja];
                    v1 = r1[ja];
                }
                __half2 h = __floats2half2_rn(v0, v1);
                *(__half2*)(sm + SM_XS + q * 128 +
                            ((((i >> 2) ^ (q & 7)) << 4) | ((i & 3) << 2))) = h;
            }
        }
    }

    // ---- interp params (packed: j0|j1<<16, f as fp16) ----
    const float* offb = off + ((size_t)b * L_ + lo0) * KK;
    for (int idx = t; idx < TP * KK; idx += NTHR) {
        int p = idx / KK;
        int k = idx % KK;
        float T = (float)(lo0 + p + k) + offb[idx];
        T = fminf(fmaxf(T, 0.0f), (float)(LP - 1));
        int i0 = (int)floorf(T);
        i0 = min(max(i0, 0), LP - 2);
        float f = T - (float)i0;
        int j0 = i0 - PAD_;
        int j1 = i0 + 1 - PAD_;
        j0 = (j0 < 0) ? -j0 : j0;
        j1 = (j1 < 0) ? -j1 : j1;
        if (j0 >= L_) j0 = 2 * L_ - 2 - j0;
        if (j1 >= L_) j1 = 2 * L_ - 2 - j1;
        j0 -= base;
        j1 -= base;
        uint2 pr;
        pr.x = ((uint32_t)j0 & 0xFFFF) | (((uint32_t)j1 & 0xFFFF) << 16);
        pr.y = (uint32_t)__half_as_ushort(__float2half_rn(f));
        par[k * TP + p] = pr;
    }
    __syncthreads();

    build_tap(sm, xb, base, 0, 0, t);
    __syncthreads();

    // warp tiling: 8 (M) x 2 (N), warp tile 32x32
    const int m0 = (wid & 7) * 32;
    const int n0 = (wid >> 3) * 32;

    float acc[2][4][4];
    #pragma unroll
    for (int i = 0; i < 2; i++)
        #pragma unroll
        for (int j = 0; j < 4; j++)
            #pragma unroll
            for (int r = 0; r < 4; r++) acc[i][j][r] = 0.0f;

    for (int tap = 0; tap < KK; tap++) {
        if (tap < KK - 1)
            build_tap(sm, xb, base, tap + 1, (tap + 1) & 1, t);

        const char* A = sm + SM_A + (tap & 1) * A_STR;
        const uint4* wfb = g_wf + (size_t)(tap * 2 + (n0 >> 5)) * 8 * 32;
        #pragma unroll
        for (int ks = 0; ks < 4; ks++) {
            uint32_t a[2][4];
            int arow = lane & 15;
            int acb  = ks * 32 + (lane >> 4) * 16;
            #pragma unroll
            for (int mi = 0; mi < 2; mi++) {
                int row = m0 + mi * 16 + arow;
                ldm_x4(a[mi][0], a[mi][1], a[mi][2], a[mi][3],
                       A + row * 128 + SWZ16(acb, arow));
            }
            uint4 Ua = __ldg(wfb + (ks * 2 + 0) * 32 + lane);   // ni 0,1
            uint4 Ub = __ldg(wfb + (ks * 2 + 1) * 32 + lane);   // ni 2,3
            #pragma unroll
            for (int mi = 0; mi < 2; mi++) {
                mma_fp16(acc[mi][0], a[mi], Ua.x, Ua.y);
                mma_fp16(acc[mi][1], a[mi], Ua.z, Ua.w);
                mma_fp16(acc[mi][2], a[mi], Ub.x, Ub.y);
                mma_fp16(acc[mi][3], a[mi], Ub.z, Ub.w);
            }
        }
        __syncthreads();
    }

    // ---- epilogue: direct stores (full 32B-sector utilization per STG) ----
    {
        const int g  = lane >> 2;
        const int tc = lane & 3;
        float* ob = out + (size_t)b * COUT * L_ + lo0;
        #pragma unroll
        for (int ni = 0; ni < 4; ni++) {
            int n = n0 + ni * 8 + tc * 2;
            float bs0 = __ldg(&bias[n]);
            float bs1 = __ldg(&bias[n + 1]);
            #pragma unroll
            for (int mi = 0; mi < 2; mi++) {
                int m = m0 + mi * 16 + g;
                ob[(size_t)n * L_ + m]           = acc[mi][ni][0] + bs0;
                ob[(size_t)(n + 1) * L_ + m]     = acc[mi][ni][1] + bs1;
                ob[(size_t)n * L_ + m + 8]       = acc[mi][ni][2] + bs0;
                ob[(size_t)(n + 1) * L_ + m + 8] = acc[mi][ni][3] + bs1;
            }
        }
    }
}

// ---------------------------------------------------------------------------
extern "C" void kernel_launch(void* const* d_in, const int* in_sizes, int n_in,
                              void* d_out, int out_size) {
    const float* x      = (const float*)d_in[0];
    const float* off    = (const float*)d_in[1];
    const float* weight = (const float*)d_in[2];
    const float* bias   = (const float*)d_in[3];
    float* out          = (float*)d_out;

    static bool attr_set = false;
    if (!attr_set) {
        cudaFuncSetAttribute(deform_main_kernel,
                             cudaFuncAttributeMaxDynamicSharedMemorySize, SM_TOTAL);
        attr_set = true;
    }

    wfrag_kernel<<<10, 256>>>(weight);

    dim3 mg(L_ / TP, B_);
    deform_main_kernel<<<mg, NTHR, SM_TOTAL>>>(x, off, bias, out);
}

// round 14
// speedup vs baseline: 1.0301x; 1.0301x over previous
#include <cuda_runtime.h>
#include <cuda_fp16.h>
#include <cstdint>

// Problem constants
#define B_    8
#define CIN   64
#define COUT  64
#define L_    16384
#define KK    5
#define PAD_  2
#define LP    (L_ + 2*PAD_)
#define TP    128
#define NTHR  256

// x slice in smem (fp16, 128B rows, XOR-swizzled 16B units)
#define SPAN  142
#define MARG  6          // base = lo0 - MARG

// smem byte offsets
#define SM_XS    0                 // 142*128 = 18176 -> 18432
#define SM_A     18432             // 2 bufs * 128 rows * 128B = 32768
#define SM_PAR   51200             // 5*128*8 = 5120
#define SM_TOTAL 56320
#define A_STR    16384

// swizzle of 16B units within a 128B row
#define SWZ16(col, row) ((col) ^ (((row) & 7) * 16))

// W in mma-B fragment order: [tap][ngrp][ks][h][lane] -> uint4
__device__ uint4 g_wf[KK * 2 * 4 * 2 * 32];

// ---------------------------------------------------------------------------
// weight (o,c,k) -> fragment-ordered fp16
// ---------------------------------------------------------------------------
__global__ void wfrag_kernel(const float* __restrict__ w) {
    int idx = blockIdx.x * 256 + threadIdx.x;    // 2560 entries
    if (idx >= 2560) return;
    int lane = idx & 31;
    int h    = (idx >> 5) & 1;
    int ks   = (idx >> 6) & 3;
    int ngrp = (idx >> 8) & 1;
    int tap  = idx >> 9;
    int bn = lane >> 2;
    int q2 = (lane & 3) * 2;
    uint32_t r[4];
    #pragma unroll
    for (int j = 0; j < 2; j++) {
        int n = ngrp * 32 + (h * 2 + j) * 8 + bn;
        #pragma unroll
        for (int hf = 0; hf < 2; hf++) {
            int c0 = ks * 16 + hf * 8 + q2;
            __half2 p;
            p.x = __float2half_rn(w[n * (CIN * KK) + c0 * KK + tap]);
            p.y = __float2half_rn(w[n * (CIN * KK) + (c0 + 1) * KK + tap]);
            r[j * 2 + hf] = *(uint32_t*)&p;
        }
    }
    g_wf[idx] = make_uint4(r[0], r[1], r[2], r[3]);
}

// ---------------------------------------------------------------------------
__device__ __forceinline__ void ldm_x4(uint32_t& r0, uint32_t& r1, uint32_t& r2, uint32_t& r3,
                                       const void* p) {
    uint32_t a = (uint32_t)__cvta_generic_to_shared(p);
    asm volatile("ldmatrix.sync.aligned.m8n8.x4.shared.b16 {%0,%1,%2,%3}, [%4];"
                 : "=r"(r0), "=r"(r1), "=r"(r2), "=r"(r3) : "r"(a));
}

__device__ __forceinline__ void mma_fp16(float* c, const uint32_t* a,
                                         uint32_t b0, uint32_t b1) {
    asm volatile(
        "mma.sync.aligned.m16n8k16.row.col.f32.f16.f16.f32 "
        "{%0,%1,%2,%3}, {%4,%5,%6,%7}, {%8,%9}, {%0,%1,%2,%3};"
        : "+f"(c[0]), "+f"(c[1]), "+f"(c[2]), "+f"(c[3])
        : "r"(a[0]), "r"(a[1]), "r"(a[2]), "r"(a[3]), "r"(b0), "r"(b1));
}

// ---------------------------------------------------------------------------
// build full-tap A tile (128 pos x 64 ch). 8 channels/thread, LDS.128 gathers.
// ---------------------------------------------------------------------------
__device__ __forceinline__ void build_tap(char* sm, const float* __restrict__ xb,
                                          int base, int tap, int buf, int t) {
    const int cq = t & 7;           // 8 channels: 8*cq .. 8*cq+7
    const int pb = t >> 3;          // 32 position groups
    const uint2* par = (const uint2*)(sm + SM_PAR) + tap * TP;
    char* A = sm + SM_A + buf * A_STR;
    const int cabs = cq * 8;
    const int swc  = SWZ16(cq * 16, pb);   // p&7 == pb&7 (pi stride 32)

    #pragma unroll
    for (int pi = 0; pi < 4; pi++) {
        int p = pb + pi * 32;
        uint2 pr = par[p];
        int j0 = (int)(short)(pr.x & 0xFFFF);
        int j1 = (int)(short)(pr.x >> 16);
        __half2 f2 = __half2half2(__ushort_as_half((unsigned short)pr.y));
        uint4 u0, u1;
        if (__builtin_expect((unsigned)j0 < SPAN, 1)) {
            u0 = *(const uint4*)(sm + SM_XS + j0 * 128 + SWZ16(cq * 16, j0));
        } else {
            int ja = min(max(j0 + base, 0), L_ - 1);
            __half2 h01 = __floats2half2_rn(xb[(size_t)cabs * L_ + ja],
                                            xb[(size_t)(cabs + 1) * L_ + ja]);
            __half2 h23 = __floats2half2_rn(xb[(size_t)(cabs + 2) * L_ + ja],
                                            xb[(size_t)(cabs + 3) * L_ + ja]);
            __half2 h45 = __floats2half2_rn(xb[(size_t)(cabs + 4) * L_ + ja],
                                            xb[(size_t)(cabs + 5) * L_ + ja]);
            __half2 h67 = __floats2half2_rn(xb[(size_t)(cabs + 6) * L_ + ja],
                                            xb[(size_t)(cabs + 7) * L_ + ja]);
            u0.x = *(uint32_t*)&h01; u0.y = *(uint32_t*)&h23;
            u0.z = *(uint32_t*)&h45; u0.w = *(uint32_t*)&h67;
        }
        if (__builtin_expect((unsigned)j1 < SPAN, 1)) {
            u1 = *(const uint4*)(sm + SM_XS + j1 * 128 + SWZ16(cq * 16, j1));
        } else {
            int ja = min(max(j1 + base, 0), L_ - 1);
            __half2 h01 = __floats2half2_rn(xb[(size_t)cabs * L_ + ja],
                                            xb[(size_t)(cabs + 1) * L_ + ja]);
            __half2 h23 = __floats2half2_rn(xb[(size_t)(cabs + 2) * L_ + ja],
                                            xb[(size_t)(cabs + 3) * L_ + ja]);
            __half2 h45 = __floats2half2_rn(xb[(size_t)(cabs + 4) * L_ + ja],
                                            xb[(size_t)(cabs + 5) * L_ + ja]);
            __half2 h67 = __floats2half2_rn(xb[(size_t)(cabs + 6) * L_ + ja],
                                            xb[(size_t)(cabs + 7) * L_ + ja]);
            u1.x = *(uint32_t*)&h01; u1.y = *(uint32_t*)&h23;
            u1.z = *(uint32_t*)&h45; u1.w = *(uint32_t*)&h67;
        }
        __half2 g0, g1;
        uint4 st;
        g0 = *(__half2*)&u0.x; g1 = *(__half2*)&u1.x;
        { __half2 v = __hfma2(f2, __hsub2(g1, g0), g0); st.x = *(uint32_t*)&v; }
        g0 = *(__half2*)&u0.y; g1 = *(__half2*)&u1.y;
        { __half2 v = __hfma2(f2, __hsub2(g1, g0), g0); st.y = *(uint32_t*)&v; }
        g0 = *(__half2*)&u0.z; g1 = *(__half2*)&u1.z;
        { __half2 v = __hfma2(f2, __hsub2(g1, g0), g0); st.z = *(uint32_t*)&v; }
        g0 = *(__half2*)&u0.w; g1 = *(__half2*)&u1.w;
        { __half2 v = __hfma2(f2, __hsub2(g1, g0), g0); st.w = *(uint32_t*)&v; }
        *(uint4*)(A + p * 128 + swc) = st;
    }
}

// ---------------------------------------------------------------------------
__global__ __launch_bounds__(NTHR, 4) void deform_main_kernel(
    const float* __restrict__ x,
    const float* __restrict__ off,
    const float* __restrict__ bias,
    float* __restrict__ out)
{
    extern __shared__ char sm[];

    const int b    = blockIdx.y;
    const int lo0  = blockIdx.x * TP;
    const int t    = threadIdx.x;
    const int lane = t & 31;
    const int wid  = t >> 5;
    const int base = lo0 - MARG;

    const float* xb = x + (size_t)b * CIN * L_;
    uint2* par = (uint2*)(sm + SM_PAR);

    // ---- x slice -> fp16 swizzled smem ----
    {
        bool interior = (base >= 0) && (base + SPAN <= L_);
        for (int i = wid; i < 32; i += 8) {           // channel pair i: ch 2i, 2i+1
            const float* r0 = xb + (size_t)(2 * i) * L_;
            const float* r1 = r0 + L_;
            for (int q = lane; q < SPAN; q += 32) {
                float v0, v1;
                if (interior) {
                    v0 = r0[base + q];
                    v1 = r1[base + q];
                } else {
                    int ja = min(max(base + q, 0), L_ - 1);
                    v0 = r0[ja];
                    v1 = r1[ja];
                }
                __half2 h = __floats2half2_rn(v0, v1);
                *(__half2*)(sm + SM_XS + q * 128 +
                            ((((i >> 2) ^ (q & 7)) << 4) | ((i & 3) << 2))) = h;
            }
        }
    }

    // ---- interp params (packed: j0|j1<<16, f as fp16) ----
    const float* offb = off + ((size_t)b * L_ + lo0) * KK;
    for (int idx = t; idx < TP * KK; idx += NTHR) {
        int p = idx / KK;
        int k = idx % KK;
        float T = (float)(lo0 + p + k) + offb[idx];
        T = fminf(fmaxf(T, 0.0f), (float)(LP - 1));
        int i0 = (int)floorf(T);
        i0 = min(max(i0, 0), LP - 2);
        float f = T - (float)i0;
        int j0 = i0 - PAD_;
        int j1 = i0 + 1 - PAD_;
        j0 = (j0 < 0) ? -j0 : j0;
        j1 = (j1 < 0) ? -j1 : j1;
        if (j0 >= L_) j0 = 2 * L_ - 2 - j0;
        if (j1 >= L_) j1 = 2 * L_ - 2 - j1;
        j0 -= base;
        j1 -= base;
        uint2 pr;
        pr.x = ((uint32_t)j0 & 0xFFFF) | (((uint32_t)j1 & 0xFFFF) << 16);
        pr.y = (uint32_t)__half_as_ushort(__float2half_rn(f));
        par[k * TP + p] = pr;
    }
    __syncthreads();

    build_tap(sm, xb, base, 0, 0, t);
    __syncthreads();

    // warp tiling: 8 (M) x 1 (N) — each warp: 16 positions x all 64 outputs
    const int m0 = wid * 16;

    float acc[8][4];
    #pragma unroll
    for (int j = 0; j < 8; j++)
        #pragma unroll
        for (int r = 0; r < 4; r++) acc[j][r] = 0.0f;

    for (int tap = 0; tap < KK; tap++) {
        if (tap < KK - 1)
            build_tap(sm, xb, base, tap + 1, (tap + 1) & 1, t);

        const char* A = sm + SM_A + (tap & 1) * A_STR;
        const uint4* wfb = g_wf + (size_t)tap * 2 * 8 * 32;
        #pragma unroll
        for (int ks = 0; ks < 4; ks++) {
            // W fragments first (LDG latency overlaps the LDS chain)
            uint4 U0 = __ldg(wfb + (0 * 8 + ks * 2 + 0) * 32 + lane);   // n 0..15
            uint4 U1 = __ldg(wfb + (0 * 8 + ks * 2 + 1) * 32 + lane);   // n 16..31
            uint4 U2 = __ldg(wfb + (1 * 8 + ks * 2 + 0) * 32 + lane);   // n 32..47
            uint4 U3 = __ldg(wfb + (1 * 8 + ks * 2 + 1) * 32 + lane);   // n 48..63
            uint32_t a[4];
            int arow = lane & 15;
            int acb  = ks * 32 + (lane >> 4) * 16;
            ldm_x4(a[0], a[1], a[2], a[3],
                   A + (m0 + arow) * 128 + SWZ16(acb, arow));
            mma_fp16(acc[0], a, U0.x, U0.y);
            mma_fp16(acc[1], a, U0.z, U0.w);
            mma_fp16(acc[2], a, U1.x, U1.y);
            mma_fp16(acc[3], a, U1.z, U1.w);
            mma_fp16(acc[4], a, U2.x, U2.y);
            mma_fp16(acc[5], a, U2.z, U2.w);
            mma_fp16(acc[6], a, U3.x, U3.y);
            mma_fp16(acc[7], a, U3.z, U3.w);
        }
        if (tap < KK - 1) __syncthreads();
    }

    // ---- epilogue: direct stores (full 32B-sector utilization per STG) ----
    {
        const int g  = lane >> 2;
        const int tc = lane & 3;
        float* ob = out + (size_t)b * COUT * L_ + lo0;
        #pragma unroll
        for (int ni = 0; ni < 8; ni++) {
            int n = ni * 8 + tc * 2;
            float bs0 = __ldg(&bias[n]);
            float bs1 = __ldg(&bias[n + 1]);
            int m = m0 + g;
            ob[(size_t)n * L_ + m]           = acc[ni][0] + bs0;
            ob[(size_t)(n + 1) * L_ + m]     = acc[ni][1] + bs1;
            ob[(size_t)n * L_ + m + 8]       = acc[ni][2] + bs0;
            ob[(size_t)(n + 1) * L_ + m + 8] = acc[ni][3] + bs1;
        }
    }
}

// ---------------------------------------------------------------------------
extern "C" void kernel_launch(void* const* d_in, const int* in_sizes, int n_in,
                              void* d_out, int out_size) {
    const float* x      = (const float*)d_in[0];
    const float* off    = (const float*)d_in[1];
    const float* weight = (const float*)d_in[2];
    const float* bias   = (const float*)d_in[3];
    float* out          = (float*)d_out;

    static bool attr_set = false;
    if (!attr_set) {
        cudaFuncSetAttribute(deform_main_kernel,
                             cudaFuncAttributeMaxDynamicSharedMemorySize, SM_TOTAL);
        attr_set = true;
    }

    wfrag_kernel<<<10, 256>>>(weight);

    dim3 mg(L_ / TP, B_);
    deform_main_kernel<<<mg, NTHR, SM_TOTAL>>>(x, off, bias, out);
}

// round 15
// speedup vs baseline: 1.0556x; 1.0247x over previous
#include <cuda_runtime.h>
#include <cuda_fp16.h>
#include <cstdint>

// Problem constants
#define B_    8
#define CIN   64
#define COUT  64
#define L_    16384
#define KK    5
#define PAD_  2
#define LP    (L_ + 2*PAD_)
#define TP    128
#define NTHR  256

// x slice in smem (fp16, 128B rows, XOR-swizzled 16B units)
#define SPAN  142
#define MARG  6          // base = lo0 - MARG

// smem byte offsets
#define SM_XS    0                 // 142*128 = 18176 -> 18432
#define SM_A     18432             // 2 bufs * 128 rows * 128B = 32768
#define SM_PAR   51200             // 5*128*8 = 5120
#define SM_TOTAL 56320
#define A_STR    16384

// swizzle of 16B units within a 128B row
#define SWZ16(col, row) ((col) ^ (((row) & 7) * 16))

// W in mma-B fragment order: [tap][ngrp][ks][h][lane] -> uint4
__device__ uint4 g_wf[KK * 2 * 4 * 2 * 32];

// ---------------------------------------------------------------------------
// weight (o,c,k) -> fragment-ordered fp16
// ---------------------------------------------------------------------------
__global__ void wfrag_kernel(const float* __restrict__ w) {
    int idx = blockIdx.x * 256 + threadIdx.x;    // 2560 entries
    if (idx >= 2560) return;
    int lane = idx & 31;
    int h    = (idx >> 5) & 1;
    int ks   = (idx >> 6) & 3;
    int ngrp = (idx >> 8) & 1;
    int tap  = idx >> 9;
    int bn = lane >> 2;
    int q2 = (lane & 3) * 2;
    uint32_t r[4];
    #pragma unroll
    for (int j = 0; j < 2; j++) {
        int n = ngrp * 32 + (h * 2 + j) * 8 + bn;
        #pragma unroll
        for (int hf = 0; hf < 2; hf++) {
            int c0 = ks * 16 + hf * 8 + q2;
            __half2 p;
            p.x = __float2half_rn(w[n * (CIN * KK) + c0 * KK + tap]);
            p.y = __float2half_rn(w[n * (CIN * KK) + (c0 + 1) * KK + tap]);
            r[j * 2 + hf] = *(uint32_t*)&p;
        }
    }
    g_wf[idx] = make_uint4(r[0], r[1], r[2], r[3]);
}

// ---------------------------------------------------------------------------
__device__ __forceinline__ void ldm_x4(uint32_t& r0, uint32_t& r1, uint32_t& r2, uint32_t& r3,
                                       const void* p) {
    uint32_t a = (uint32_t)__cvta_generic_to_shared(p);
    asm volatile("ldmatrix.sync.aligned.m8n8.x4.shared.b16 {%0,%1,%2,%3}, [%4];"
                 : "=r"(r0), "=r"(r1), "=r"(r2), "=r"(r3) : "r"(a));
}

__device__ __forceinline__ void mma_fp16(float* c, const uint32_t* a,
                                         uint32_t b0, uint32_t b1) {
    asm volatile(
        "mma.sync.aligned.m16n8k16.row.col.f32.f16.f16.f32 "
        "{%0,%1,%2,%3}, {%4,%5,%6,%7}, {%8,%9}, {%0,%1,%2,%3};"
        : "+f"(c[0]), "+f"(c[1]), "+f"(c[2]), "+f"(c[3])
        : "r"(a[0]), "r"(a[1]), "r"(a[2]), "r"(a[3]), "r"(b0), "r"(b1));
}

// ---------------------------------------------------------------------------
// build full-tap A tile (128 pos x 64 ch). 8 channels/thread, LDS.128 gathers.
// Param loads hoisted to batch gather MLP.
// ---------------------------------------------------------------------------
__device__ __forceinline__ void build_tap(char* sm, const float* __restrict__ xb,
                                          int base, int tap, int buf, int t) {
    const int cq = t & 7;           // 8 channels: 8*cq .. 8*cq+7
    const int pb = t >> 3;          // 32 position groups
    const uint2* par = (const uint2*)(sm + SM_PAR) + tap * TP;
    char* A = sm + SM_A + buf * A_STR;
    const int cabs = cq * 8;
    const int swc  = SWZ16(cq * 16, pb);   // p&7 == pb&7 (pi stride 32)

    // hoisted param loads (batches the gather chain)
    uint2 pr[4];
    #pragma unroll
    for (int pi = 0; pi < 4; pi++)
        pr[pi] = par[pb + pi * 32];

    #pragma unroll
    for (int pi = 0; pi < 4; pi++) {
        int p = pb + pi * 32;
        int j0 = (int)(short)(pr[pi].x & 0xFFFF);
        int j1 = (int)(short)(pr[pi].x >> 16);
        __half2 f2 = __half2half2(__ushort_as_half((unsigned short)pr[pi].y));
        uint4 u0, u1;
        if (__builtin_expect((unsigned)j0 < SPAN, 1)) {
            u0 = *(const uint4*)(sm + SM_XS + j0 * 128 + SWZ16(cq * 16, j0));
        } else {
            int ja = min(max(j0 + base, 0), L_ - 1);
            __half2 h01 = __floats2half2_rn(xb[(size_t)cabs * L_ + ja],
                                            xb[(size_t)(cabs + 1) * L_ + ja]);
            __half2 h23 = __floats2half2_rn(xb[(size_t)(cabs + 2) * L_ + ja],
                                            xb[(size_t)(cabs + 3) * L_ + ja]);
            __half2 h45 = __floats2half2_rn(xb[(size_t)(cabs + 4) * L_ + ja],
                                            xb[(size_t)(cabs + 5) * L_ + ja]);
            __half2 h67 = __floats2half2_rn(xb[(size_t)(cabs + 6) * L_ + ja],
                                            xb[(size_t)(cabs + 7) * L_ + ja]);
            u0.x = *(uint32_t*)&h01; u0.y = *(uint32_t*)&h23;
            u0.z = *(uint32_t*)&h45; u0.w = *(uint32_t*)&h67;
        }
        if (__builtin_expect((unsigned)j1 < SPAN, 1)) {
            u1 = *(const uint4*)(sm + SM_XS + j1 * 128 + SWZ16(cq * 16, j1));
        } else {
            int ja = min(max(j1 + base, 0), L_ - 1);
            __half2 h01 = __floats2half2_rn(xb[(size_t)cabs * L_ + ja],
                                            xb[(size_t)(cabs + 1) * L_ + ja]);
            __half2 h23 = __floats2half2_rn(xb[(size_t)(cabs + 2) * L_ + ja],
                                            xb[(size_t)(cabs + 3) * L_ + ja]);
            __half2 h45 = __floats2half2_rn(xb[(size_t)(cabs + 4) * L_ + ja],
                                            xb[(size_t)(cabs + 5) * L_ + ja]);
            __half2 h67 = __floats2half2_rn(xb[(size_t)(cabs + 6) * L_ + ja],
                                            xb[(size_t)(cabs + 7) * L_ + ja]);
            u1.x = *(uint32_t*)&h01; u1.y = *(uint32_t*)&h23;
            u1.z = *(uint32_t*)&h45; u1.w = *(uint32_t*)&h67;
        }
        __half2 g0, g1;
        uint4 st;
        g0 = *(__half2*)&u0.x; g1 = *(__half2*)&u1.x;
        { __half2 v = __hfma2(f2, __hsub2(g1, g0), g0); st.x = *(uint32_t*)&v; }
        g0 = *(__half2*)&u0.y; g1 = *(__half2*)&u1.y;
        { __half2 v = __hfma2(f2, __hsub2(g1, g0), g0); st.y = *(uint32_t*)&v; }
        g0 = *(__half2*)&u0.z; g1 = *(__half2*)&u1.z;
        { __half2 v = __hfma2(f2, __hsub2(g1, g0), g0); st.z = *(uint32_t*)&v; }
        g0 = *(__half2*)&u0.w; g1 = *(__half2*)&u1.w;
        { __half2 v = __hfma2(f2, __hsub2(g1, g0), g0); st.w = *(uint32_t*)&v; }
        *(uint4*)(A + p * 128 + swc) = st;
    }
}

// ---------------------------------------------------------------------------
__global__ __launch_bounds__(NTHR, 4) void deform_main_kernel(
    const float* __restrict__ x,
    const float* __restrict__ off,
    const float* __restrict__ bias,
    float* __restrict__ out)
{
    extern __shared__ char sm[];

    const int b    = blockIdx.y;
    const int lo0  = blockIdx.x * TP;
    const int t    = threadIdx.x;
    const int lane = t & 31;
    const int wid  = t >> 5;
    const int base = lo0 - MARG;

    const float* xb = x + (size_t)b * CIN * L_;
    uint2* par = (uint2*)(sm + SM_PAR);

    // ---- x slice -> fp16 swizzled smem ----
    {
        bool interior = (base >= 0) && (base + SPAN <= L_);
        for (int i = wid; i < 32; i += 8) {           // channel pair i: ch 2i, 2i+1
            const float* r0 = xb + (size_t)(2 * i) * L_;
            const float* r1 = r0 + L_;
            for (int q = lane; q < SPAN; q += 32) {
                float v0, v1;
                if (interior) {
                    v0 = r0[base + q];
                    v1 = r1[base + q];
                } else {
                    int ja = min(max(base + q, 0), L_ - 1);
                    v0 = r0[ja];
                    v1 = r1[ja];
                }
                __half2 h = __floats2half2_rn(v0, v1);
                *(__half2*)(sm + SM_XS + q * 128 +
                            ((((i >> 2) ^ (q & 7)) << 4) | ((i & 3) << 2))) = h;
            }
        }
    }

    // ---- interp params (packed: j0|j1<<16, f as fp16) ----
    const float* offb = off + ((size_t)b * L_ + lo0) * KK;
    for (int idx = t; idx < TP * KK; idx += NTHR) {
        int p = idx / KK;
        int k = idx % KK;
        float T = (float)(lo0 + p + k) + offb[idx];
        T = fminf(fmaxf(T, 0.0f), (float)(LP - 1));
        int i0 = (int)floorf(T);
        i0 = min(max(i0, 0), LP - 2);
        float f = T - (float)i0;
        int j0 = i0 - PAD_;
        int j1 = i0 + 1 - PAD_;
        j0 = (j0 < 0) ? -j0 : j0;
        j1 = (j1 < 0) ? -j1 : j1;
        if (j0 >= L_) j0 = 2 * L_ - 2 - j0;
        if (j1 >= L_) j1 = 2 * L_ - 2 - j1;
        j0 -= base;
        j1 -= base;
        uint2 pr;
        pr.x = ((uint32_t)j0 & 0xFFFF) | (((uint32_t)j1 & 0xFFFF) << 16);
        pr.y = (uint32_t)__half_as_ushort(__float2half_rn(f));
        par[k * TP + p] = pr;
    }
    __syncthreads();

    build_tap(sm, xb, base, 0, 0, t);
    __syncthreads();

    // warp tiling: 4 (M) x 2 (N), warp tile 32x32
    const int m0 = (wid & 3) * 32;
    const int n0 = (wid >> 2) * 32;

    float acc[2][4][4];
    #pragma unroll
    for (int i = 0; i < 2; i++)
        #pragma unroll
        for (int j = 0; j < 4; j++)
            #pragma unroll
            for (int r = 0; r < 4; r++) acc[i][j][r] = 0.0f;

    for (int tap = 0; tap < KK; tap++) {
        if (tap < KK - 1)
            build_tap(sm, xb, base, tap + 1, (tap + 1) & 1, t);

        const char* A = sm + SM_A + (tap & 1) * A_STR;
        const uint4* wfb = g_wf + (size_t)(tap * 2 + (n0 >> 5)) * 8 * 32;
        #pragma unroll
        for (int ks = 0; ks < 4; ks++) {
            // W fragments first: LDG latency overlaps the ldmatrix LDS chain
            uint4 Ua = __ldg(wfb + (ks * 2 + 0) * 32 + lane);   // ni 0,1
            uint4 Ub = __ldg(wfb + (ks * 2 + 1) * 32 + lane);   // ni 2,3
            uint32_t a[2][4];
            int arow = lane & 15;
            int acb  = ks * 32 + (lane >> 4) * 16;
            #pragma unroll
            for (int mi = 0; mi < 2; mi++) {
                int row = m0 + mi * 16 + arow;
                ldm_x4(a[mi][0], a[mi][1], a[mi][2], a[mi][3],
                       A + row * 128 + SWZ16(acb, arow));
            }
            #pragma unroll
            for (int mi = 0; mi < 2; mi++) {
                mma_fp16(acc[mi][0], a[mi], Ua.x, Ua.y);
                mma_fp16(acc[mi][1], a[mi], Ua.z, Ua.w);
                mma_fp16(acc[mi][2], a[mi], Ub.x, Ub.y);
                mma_fp16(acc[mi][3], a[mi], Ub.z, Ub.w);
            }
        }
        if (tap < KK - 1) __syncthreads();
    }

    // ---- epilogue: direct stores (full 32B-sector utilization per STG) ----
    {
        const int g  = lane >> 2;
        const int tc = lane & 3;
        float* ob = out + (size_t)b * COUT * L_ + lo0;
        #pragma unroll
        for (int ni = 0; ni < 4; ni++) {
            int n = n0 + ni * 8 + tc * 2;
            float bs0 = __ldg(&bias[n]);
            float bs1 = __ldg(&bias[n + 1]);
            #pragma unroll
            for (int mi = 0; mi < 2; mi++) {
                int m = m0 + mi * 16 + g;
                ob[(size_t)n * L_ + m]           = acc[mi][ni][0] + bs0;
                ob[(size_t)(n + 1) * L_ + m]     = acc[mi][ni][1] + bs1;
                ob[(size_t)n * L_ + m + 8]       = acc[mi][ni][2] + bs0;
                ob[(size_t)(n + 1) * L_ + m + 8] = acc[mi][ni][3] + bs1;
            }
        }
    }
}

// ---------------------------------------------------------------------------
extern "C" void kernel_launch(void* const* d_in, const int* in_sizes, int n_in,
                              void* d_out, int out_size) {
    const float* x      = (const float*)d_in[0];
    const float* off    = (const float*)d_in[1];
    const float* weight = (const float*)d_in[2];
    const float* bias   = (const float*)d_in[3];
    float* out          = (float*)d_out;

    static bool attr_set = false;
    if (!attr_set) {
        cudaFuncSetAttribute(deform_main_kernel,
                             cudaFuncAttributeMaxDynamicSharedMemorySize, SM_TOTAL);
        attr_set = true;
    }

    wfrag_kernel<<<10, 256>>>(weight);

    dim3 mg(L_ / TP, B_);
    deform_main_kernel<<<mg, NTHR, SM_TOTAL>>>(x, off, bias, out);
}